// round 1
// baseline (speedup 1.0000x reference)
#include <cuda_runtime.h>
#include <cstdint>

// Problem constants (fixed by setup_inputs)
#define NB      4
#define NPTS    8192
#define NPOINT  2048
#define KNN_K   20
#define CFEAT   128
#define CIN     131      // feat(128) + xyz(3)
#define COUT    256
#define BN_EPS  1e-5f
#define TOTAL_CNT (NB*NPOINT*KNN_K)   // 163840

// ---------------- device scratch (allocation-free rule: __device__ globals) ----
__device__ float g_G[NB*NPTS*COUT];       // feat_aug @ Wa   (33.5 MB)
__device__ float g_CT[NB*NPOINT*COUT];    // center @ (Wb-Wa) (8.4 MB)
__device__ float g_Wd[CIN*COUT];          // Wb - Wa
__device__ int   g_sidx[NB*NPOINT];
__device__ int   g_knn[NB*NPOINT*KNN_K];
__device__ float g_sum[COUT];
__device__ float g_sumsq[COUT];

// ---------------- small helpers ------------------------------------------------
__global__ void zero_stats_kernel() {
    int t = threadIdx.x;
    if (t < COUT) { g_sum[t] = 0.0f; g_sumsq[t] = 0.0f; }
}

__global__ void wd_kernel(const float* __restrict__ conv_w) {
    int i = blockIdx.x * blockDim.x + threadIdx.x;
    if (i < CIN*COUT) g_Wd[i] = conv_w[CIN*COUT + i] - conv_w[i];
}

// ---------------- FPS: one block per batch, serial over 2048 samples -----------
// 512 threads, 16 points/thread, blocked assignment (thread t owns [t*16,t*16+16))
// so first-set-bit == smallest index for exact argmax tie behavior.
__global__ __launch_bounds__(512)
void fps_kernel(const float* __restrict__ xyz, const int* __restrict__ init_far,
                float* __restrict__ out_xyz, float* __restrict__ out_sidx_f)
{
    extern __shared__ float smem[];
    float* sx = smem;
    float* sy = smem + NPTS;
    float* sz = smem + 2*NPTS;
    __shared__ float swv[16];
    __shared__ int   swi[16];
    __shared__ float scen[3];
    __shared__ int   sfar;

    const int b   = blockIdx.x;
    const int tid = threadIdx.x;
    const int lane = tid & 31, wid = tid >> 5;
    const float* x = xyz + (size_t)b * NPTS * 3;

    for (int i = tid; i < NPTS; i += 512) {
        sx[i] = x[3*i]; sy[i] = x[3*i+1]; sz[i] = x[3*i+2];
    }
    __syncthreads();

    float px[16], py[16], pz[16], pd[16];
#pragma unroll
    for (int i = 0; i < 16; i++) {
        int idx = tid*16 + i;
        px[i] = sx[idx]; py[i] = sy[idx]; pz[i] = sz[idx];
        pd[i] = 1e10f;
    }
    if (tid == 0) {
        int f0 = init_far[b];
        sfar = f0;
        scen[0] = sx[f0]; scen[1] = sy[f0]; scen[2] = sz[f0];
    }
    __syncthreads();

    for (int j = 0; j < NPOINT; j++) {
        int   curfar = sfar;
        float cx = scen[0], cy = scen[1], cz = scen[2];
        if (tid == 0) {
            g_sidx[b*NPOINT + j] = curfar;
            out_sidx_f[b*NPOINT + j] = (float)curfar;
            out_xyz[(b*NPOINT + j)*3 + 0] = cx;
            out_xyz[(b*NPOINT + j)*3 + 1] = cy;
            out_xyz[(b*NPOINT + j)*3 + 2] = cz;
        }
        float bestv = -1.0f; int besti = 0;
#pragma unroll
        for (int i = 0; i < 16; i++) {
            float dx = px[i]-cx, dy = py[i]-cy, dz = pz[i]-cz;
            float d = fmaf(dz, dz, fmaf(dy, dy, dx*dx));
            float nd = fminf(pd[i], d);
            pd[i] = nd;
            if (nd > bestv) { bestv = nd; besti = tid*16 + i; }
        }
        // warp argmax: value via redux (fp bits monotone, d>=0), tie -> lowest lane
        unsigned fb = __float_as_uint(bestv);
        unsigned m  = __reduce_max_sync(0xffffffffu, fb);
        unsigned tied = __ballot_sync(0xffffffffu, fb == m);
        int src = __ffs(tied) - 1;
        int wbi = __shfl_sync(0xffffffffu, besti, src);
        if (lane == 0) { swv[wid] = __uint_as_float(m); swi[wid] = wbi; }
        __syncthreads();
        if (wid == 0) {
            unsigned fb2 = (lane < 16) ? __float_as_uint(swv[lane]) : 0u;
            int bi = (lane < 16) ? swi[lane] : 0x7fffffff;
            unsigned m2 = __reduce_max_sync(0xffffffffu, fb2);
            unsigned t2 = __ballot_sync(0xffffffffu, (fb2 == m2) && (lane < 16));
            int s2 = __ffs(t2) - 1;
            int nf = __shfl_sync(0xffffffffu, bi, s2);
            if (lane == 0) {
                sfar = nf;
                scen[0] = sx[nf]; scen[1] = sy[nf]; scen[2] = sz[nf];
            }
        }
        __syncthreads();
    }
}

// ---------------- KNN: one block per query, d2 in smem, 20 min-extractions -----
__global__ __launch_bounds__(256)
void knn_kernel(const float* __restrict__ xyz)
{
    __shared__ float sd2[NPTS];
    __shared__ float swv[8];
    __shared__ int   swi[8];

    const int q   = blockIdx.x;          // b*NPOINT + s
    const int b   = q >> 11;
    const int tid = threadIdx.x;
    const float* x = xyz + (size_t)b * NPTS * 3;

    const int si = g_sidx[q];
    const float qx = x[3*si], qy = x[3*si+1], qz = x[3*si+2];

    for (int i = tid; i < NPTS; i += 256) {
        float dx = x[3*i]-qx, dy = x[3*i+1]-qy, dz = x[3*i+2]-qz;
        sd2[i] = fmaf(dz, dz, fmaf(dy, dy, dx*dx));
    }
    __syncthreads();

    for (int j = 0; j < KNN_K; j++) {
        float bv = 3.4e38f; int bi = 0x7fffffff;
#pragma unroll 8
        for (int r = 0; r < 32; r++) {
            int i = tid + (r << 8);
            float v = sd2[i];
            if (v < bv) { bv = v; bi = i; }     // strict < keeps smallest idx
        }
        unsigned fb = __float_as_uint(bv);
        unsigned m  = __reduce_min_sync(0xffffffffu, fb);
        unsigned cand = (fb == m) ? (unsigned)bi : 0xffffffffu;
        unsigned bidx = __reduce_min_sync(0xffffffffu, cand);
        int lane = tid & 31, wid = tid >> 5;
        if (lane == 0) { swv[wid] = __uint_as_float(m); swi[wid] = (int)bidx; }
        __syncthreads();
        if (tid == 0) {
            float fv = swv[0]; int fi = swi[0];
#pragma unroll
            for (int w = 1; w < 8; w++) {
                float v = swv[w]; int i2 = swi[w];
                if (v < fv || (v == fv && i2 < fi)) { fv = v; fi = i2; }
            }
            g_knn[q*KNN_K + j] = fi;
            sd2[fi] = 3.4e38f;                   // mask out
        }
        __syncthreads();
    }
}

// ---------------- SGEMM: Out[M,256] = A_virtual[M,131] @ W[131,256] ------------
// MODE 0: A row m -> (b=m>>13, n=m&8191), W = conv_w[:131], out = g_G
// MODE 1: A row m -> (b=m>>11, n=g_sidx[m]), W = g_Wd,      out = g_CT
template<int MODE>
__global__ __launch_bounds__(256)
void gemm_kernel(const float* __restrict__ feat, const float* __restrict__ xyz,
                 const float* __restrict__ conv_w)
{
    __shared__ float As[16*128];   // [k][m]
    __shared__ float Bs[16*128];   // [k][n]

    const int tid = threadIdx.x;
    const int tx = tid & 15, ty = tid >> 4;
    const int rowBase = blockIdx.y * 128;
    const int colBase = blockIdx.x * 128;
    const float* W = (MODE == 0) ? conv_w : g_Wd;
    float* out = (MODE == 0) ? g_G : g_CT;

    float acc[8][8];
#pragma unroll
    for (int i = 0; i < 8; i++)
#pragma unroll
        for (int jj = 0; jj < 8; jj++) acc[i][jj] = 0.0f;

    // precompute source row pointer for this thread's A loads
    const int ar  = tid >> 1;                // 0..127
    const int ac8 = (tid & 1) * 8;           // 0 or 8
    int grow = rowBase + ar;
    int bb, nn;
    if (MODE == 0) { bb = grow >> 13; nn = grow & 8191; }
    else           { bb = grow >> 11; nn = g_sidx[grow]; }
    const float* frow = feat + ((size_t)(bb*NPTS + nn)) * CFEAT;
    const float* xrow = xyz  + ((size_t)(bb*NPTS + nn)) * 3;

    for (int kb = 0; kb < CIN; kb += 16) {
#pragma unroll
        for (int u = 0; u < 8; u++) {
            int c = kb + ac8 + u;
            float v;
            if (c < CFEAT)      v = frow[c];
            else if (c < CIN)   v = xrow[c - CFEAT];
            else                v = 0.0f;
            As[(ac8 + u)*128 + ar] = v;
        }
        {
            int k = kb + (tid >> 4);
            int col = colBase + (tid & 15)*8;
            if (k < CIN) {
                float4 w0 = *reinterpret_cast<const float4*>(&W[k*COUT + col]);
                float4 w1 = *reinterpret_cast<const float4*>(&W[k*COUT + col + 4]);
                *reinterpret_cast<float4*>(&Bs[(tid>>4)*128 + (tid&15)*8])     = w0;
                *reinterpret_cast<float4*>(&Bs[(tid>>4)*128 + (tid&15)*8 + 4]) = w1;
            } else {
                float4 z = make_float4(0,0,0,0);
                *reinterpret_cast<float4*>(&Bs[(tid>>4)*128 + (tid&15)*8])     = z;
                *reinterpret_cast<float4*>(&Bs[(tid>>4)*128 + (tid&15)*8 + 4]) = z;
            }
        }
        __syncthreads();
#pragma unroll
        for (int kk = 0; kk < 16; kk++) {
            float4 a0 = *reinterpret_cast<const float4*>(&As[kk*128 + ty*8]);
            float4 a1 = *reinterpret_cast<const float4*>(&As[kk*128 + ty*8 + 4]);
            float4 b0 = *reinterpret_cast<const float4*>(&Bs[kk*128 + tx*8]);
            float4 b1 = *reinterpret_cast<const float4*>(&Bs[kk*128 + tx*8 + 4]);
            float av[8] = {a0.x,a0.y,a0.z,a0.w,a1.x,a1.y,a1.z,a1.w};
            float bv[8] = {b0.x,b0.y,b0.z,b0.w,b1.x,b1.y,b1.z,b1.w};
#pragma unroll
            for (int i = 0; i < 8; i++)
#pragma unroll
                for (int jj = 0; jj < 8; jj++)
                    acc[i][jj] = fmaf(av[i], bv[jj], acc[i][jj]);
        }
        __syncthreads();
    }

#pragma unroll
    for (int i = 0; i < 8; i++) {
        int orow = rowBase + ty*8 + i;
        float* op = out + (size_t)orow * COUT + colBase + tx*8;
        float4 o0 = make_float4(acc[i][0], acc[i][1], acc[i][2], acc[i][3]);
        float4 o1 = make_float4(acc[i][4], acc[i][5], acc[i][6], acc[i][7]);
        *reinterpret_cast<float4*>(op)     = o0;
        *reinterpret_cast<float4*>(op + 4) = o1;
    }
}

// ---------------- Fused gather + max-pool + BN stats ---------------------------
// 8 queries/block, thread = channel. h = G[b,knn] + CT[q]; track max, sum, sumsq.
__global__ __launch_bounds__(256)
void fuse_kernel(float* __restrict__ out_feat)
{
    const int tid = threadIdx.x;
    const int q0  = blockIdx.x * 8;
    float s1 = 0.0f, s2 = 0.0f;
    for (int jq = 0; jq < 8; jq++) {
        int q = q0 + jq;
        int b = q >> 11;
        float ct = g_CT[(size_t)q*COUT + tid];
        const int* kn = g_knn + q*KNN_K;
        float mv = -3.4e38f;
#pragma unroll
        for (int k = 0; k < KNN_K; k++) {
            int n = __ldg(kn + k);
            float g = g_G[((size_t)(b*NPTS + n))*COUT + tid];
            float h = g + ct;
            s1 += h;
            s2 = fmaf(h, h, s2);
            mv = fmaxf(mv, h);
        }
        out_feat[(size_t)q*COUT + tid] = mv;
    }
    atomicAdd(&g_sum[tid],   s1);
    atomicAdd(&g_sumsq[tid], s2);
}

// ---------------- BN apply (in place on max-pooled features) -------------------
__global__ __launch_bounds__(256)
void bn_kernel(float* __restrict__ feat, const float* __restrict__ gamma,
               const float* __restrict__ beta)
{
    int i = blockIdx.x * blockDim.x + threadIdx.x;
    int o = i & (COUT - 1);
    const float inv = 1.0f / (float)TOTAL_CNT;
    float mean = g_sum[o] * inv;
    float var  = g_sumsq[o] * inv - mean*mean;
    float sc   = rsqrtf(var + BN_EPS) * gamma[o];
    float v    = (feat[i] - mean) * sc + beta[o];
    feat[i] = fmaxf(v, 0.0f);
}

// ---------------- launch -------------------------------------------------------
extern "C" void kernel_launch(void* const* d_in, const int* in_sizes, int n_in,
                              void* d_out, int out_size)
{
    const float* xyz    = (const float*)d_in[0];
    const float* feat   = (const float*)d_in[1];
    const float* conv_w = (const float*)d_in[2];
    const float* gamma  = (const float*)d_in[3];
    const float* beta   = (const float*)d_in[4];
    const int*   initf  = (const int*)d_in[5];
    (void)in_sizes; (void)n_in; (void)out_size;

    float* out      = (float*)d_out;
    float* out_xyz  = out;                                   // [4,2048,3]
    float* out_feat = out + NB*NPOINT*3;                     // [4,2048,256]
    float* out_sidx = out + NB*NPOINT*3 + NB*NPOINT*COUT;    // [4,2048]

    cudaFuncSetAttribute(fps_kernel, cudaFuncAttributeMaxDynamicSharedMemorySize,
                         3*NPTS*sizeof(float));

    zero_stats_kernel<<<1, 256>>>();
    wd_kernel<<<(CIN*COUT + 255)/256, 256>>>(conv_w);
    fps_kernel<<<NB, 512, 3*NPTS*sizeof(float)>>>(xyz, initf, out_xyz, out_sidx);
    gemm_kernel<0><<<dim3(2, (NB*NPTS)/128), 256>>>(feat, xyz, conv_w);
    gemm_kernel<1><<<dim3(2, (NB*NPOINT)/128), 256>>>(feat, xyz, conv_w);
    knn_kernel<<<NB*NPOINT, 256>>>(xyz);
    fuse_kernel<<<(NB*NPOINT)/8, 256>>>(out_feat);
    bn_kernel<<<(NB*NPOINT*COUT)/256, 256>>>(out_feat, gamma, beta);
}

// round 7
// speedup vs baseline: 1.5895x; 1.5895x over previous
#include <cuda_runtime.h>
#include <cstdint>

#define NB      4
#define NPTS    8192
#define NPOINT  2048
#define KNN_K   20
#define CFEAT   128
#define CIN     131
#define COUT    256
#define BN_EPS  1e-5f
#define TOTAL_CNT (NB*NPOINT*KNN_K)

// ---------------- device scratch ----------------
__device__ float g_G[NB*NPTS*COUT];
__device__ float g_CT[NB*NPOINT*COUT];
__device__ float g_Wd[CIN*COUT];
__device__ int   g_sidx[NB*NPOINT];
__device__ int   g_knn[NB*NPOINT*KNN_K];
__device__ float g_sum[COUT];
__device__ float g_sumsq[COUT];

// ---------------- packed f32x2 helpers ----------------
#define ADD2(out, a, b) asm("add.rn.f32x2 %0, %1, %2;" : "=l"(out) : "l"(a), "l"(b))
#define MUL2(out, a, b) asm("mul.rn.f32x2 %0, %1, %2;" : "=l"(out) : "l"(a), "l"(b))
#define FMA2(out, a, b, c) asm("fma.rn.f32x2 %0, %1, %2, %3;" : "=l"(out) : "l"(a), "l"(b), "l"(c))

__device__ __forceinline__ unsigned long long pack2(float lo, float hi) {
    unsigned long long r;
    asm("mov.b64 %0, {%1, %2};" : "=l"(r) : "f"(lo), "f"(hi));
    return r;
}
__device__ __forceinline__ void unpack2(float& lo, float& hi, unsigned long long v) {
    asm("mov.b64 {%0, %1}, %2;" : "=f"(lo), "=f"(hi) : "l"(v));
}

// ---------------- small helpers ----------------
__global__ void zero_stats_kernel() {
    int t = threadIdx.x;
    if (t < COUT) { g_sum[t] = 0.0f; g_sumsq[t] = 0.0f; }
}

__global__ void wd_kernel(const float* __restrict__ conv_w) {
    int i = blockIdx.x * blockDim.x + threadIdx.x;
    if (i < CIN*COUT) g_Wd[i] = conv_w[CIN*COUT + i] - conv_w[i];
}

// ---------------- FPS ----------------
// 512 threads, 16 pts/thread (8 f32x2 pairs). One block per batch.
__global__ __launch_bounds__(512)
void fps_kernel(const float* __restrict__ xyz, const int* __restrict__ init_far,
                float* __restrict__ out_xyz, float* __restrict__ out_sidx_f)
{
    extern __shared__ float smem[];
    float* sx = smem;
    float* sy = smem + NPTS;
    float* sz = smem + 2*NPTS;
    __shared__ unsigned swv[16];
    __shared__ int s_cand[2];

    const int b   = blockIdx.x;
    const int tid = threadIdx.x;
    const int lane = tid & 31, wid = tid >> 5;
    const float* x = xyz + (size_t)b * NPTS * 3;

    for (int i = tid; i < NPTS; i += 512) {
        sx[i] = x[3*i]; sy[i] = x[3*i+1]; sz[i] = x[3*i+2];
    }
    if (tid == 0) { s_cand[0] = init_far[b]; s_cand[1] = 0x7fffffff; }
    __syncthreads();

    unsigned long long px2[8], py2[8], pz2[8];
    float pd[16];
#pragma unroll
    for (int p = 0; p < 8; p++) {
        int i0 = tid*16 + 2*p;
        px2[p] = pack2(sx[i0], sx[i0+1]);
        py2[p] = pack2(sy[i0], sy[i0+1]);
        pz2[p] = pack2(sz[i0], sz[i0+1]);
        pd[2*p] = 1e10f; pd[2*p+1] = 1e10f;
    }

    for (int j = 0; j < NPOINT; j++) {
        const int cur = s_cand[j & 1];
        const float cx = sx[cur], cy = sy[cur], cz = sz[cur];
        if (tid == 0) {
            s_cand[(j+1) & 1] = 0x7fffffff;
            g_sidx[b*NPOINT + j] = cur;
            out_sidx_f[b*NPOINT + j] = (float)cur;
            out_xyz[(b*NPOINT + j)*3 + 0] = cx;
            out_xyz[(b*NPOINT + j)*3 + 1] = cy;
            out_xyz[(b*NPOINT + j)*3 + 2] = cz;
        }
        const unsigned long long ncx = pack2(-cx, -cx);
        const unsigned long long ncy = pack2(-cy, -cy);
        const unsigned long long ncz = pack2(-cz, -cz);

        float bv = -1.0f;
#pragma unroll
        for (int p = 0; p < 8; p++) {
            unsigned long long dx2, dy2, dz2, s2;
            ADD2(dx2, px2[p], ncx);
            ADD2(dy2, py2[p], ncy);
            ADD2(dz2, pz2[p], ncz);
            MUL2(s2, dx2, dx2);
            FMA2(s2, dy2, dy2, s2);
            FMA2(s2, dz2, dz2, s2);
            float d0, d1; unpack2(d0, d1, s2);
            float n0 = fminf(pd[2*p],   d0); pd[2*p]   = n0;
            float n1 = fminf(pd[2*p+1], d1); pd[2*p+1] = n1;
            bv = fmaxf(bv, fmaxf(n0, n1));
        }
        const unsigned bb = __float_as_uint(bv);
        const unsigned wm = __reduce_max_sync(0xffffffffu, bb);
        if (lane == 0) swv[wid] = wm;
        __syncthreads();

        const unsigned v  = (lane < 16) ? swv[lane] : 0u;
        const unsigned gm = __reduce_max_sync(0xffffffffu, v);
        if (bb == gm) {
            int li = 0;
#pragma unroll
            for (int i = 15; i >= 0; i--)
                if (__float_as_uint(pd[i]) == gm) li = i;
            atomicMin(&s_cand[(j+1) & 1], tid*16 + li);
        }
        __syncthreads();
    }
}

// ---------------- KNN: tournament selection ----------------
__global__ __launch_bounds__(256)
void knn_kernel(const float* __restrict__ xyz)
{
    __shared__ float sd[NPTS];
    __shared__ unsigned svw[8];
    __shared__ unsigned siw[8];

    const int q   = blockIdx.x;
    const int b   = q >> 11;
    const int t   = threadIdx.x;
    const int lane = t & 31, wid = t >> 5;
    const float* x = xyz + (size_t)b * NPTS * 3;

    const int si = g_sidx[q];
    const float qx = x[3*si], qy = x[3*si+1], qz = x[3*si+2];

    float mv = 3.4e38f; int mi = 0;
#pragma unroll 4
    for (int i = 0; i < 32; i++) {
        int n = i*256 + t;
        float dx = x[3*n]-qx, dy = x[3*n+1]-qy, dz = x[3*n+2]-qz;
        float d = fmaf(dz, dz, fmaf(dy, dy, dx*dx));
        sd[n] = d;
        if (d < mv) { mv = d; mi = n; }   // strict < keeps smallest n
    }

    for (int j = 0; j < KNN_K; j++) {
        unsigned db = __float_as_uint(mv);
        unsigned wm = __reduce_min_sync(0xffffffffu, db);
        unsigned cand = (db == wm) ? (unsigned)mi : 0xffffffffu;
        unsigned wi = __reduce_min_sync(0xffffffffu, cand);
        if (lane == 0) { svw[wid] = wm; siw[wid] = wi; }
        __syncthreads();

        unsigned v  = (lane < 8) ? svw[lane] : 0xffffffffu;
        unsigned ii = (lane < 8) ? siw[lane] : 0xffffffffu;
        unsigned m2 = __reduce_min_sync(0xffffffffu, v);
        unsigned c2 = (v == m2) ? ii : 0xffffffffu;
        unsigned fi = __reduce_min_sync(0xffffffffu, c2);

        if (t == (int)(fi & 255u)) {
            g_knn[q*KNN_K + j] = (int)fi;
            sd[fi] = 3.4e38f;
            float nmv = 3.4e38f; int nmi = 0;
#pragma unroll
            for (int i = 0; i < 32; i++) {
                float vv = sd[i*256 + t];
                if (vv < nmv) { nmv = vv; nmi = i*256 + t; }
            }
            mv = nmv; mi = nmi;
        }
        __syncthreads();
    }
}

// ---------------- SGEMM ----------------
template<int MODE>
__global__ __launch_bounds__(256)
void gemm_kernel(const float* __restrict__ feat, const float* __restrict__ xyz,
                 const float* __restrict__ conv_w)
{
    __shared__ float As[16*128];
    __shared__ float Bs[16*128];

    const int tid = threadIdx.x;
    const int tx = tid & 15, ty = tid >> 4;
    const int rowBase = blockIdx.y * 128;
    const int colBase = blockIdx.x * 128;
    const float* W = (MODE == 0) ? conv_w : g_Wd;
    float* out = (MODE == 0) ? g_G : g_CT;

    float acc[8][8];
#pragma unroll
    for (int i = 0; i < 8; i++)
#pragma unroll
        for (int jj = 0; jj < 8; jj++) acc[i][jj] = 0.0f;

    const int ar  = tid >> 1;
    const int ac8 = (tid & 1) * 8;
    int grow = rowBase + ar;
    int bb, nn;
    if (MODE == 0) { bb = grow >> 13; nn = grow & 8191; }
    else           { bb = grow >> 11; nn = g_sidx[grow]; }
    const float* frow = feat + ((size_t)(bb*NPTS + nn)) * CFEAT;
    const float* xrow = xyz  + ((size_t)(bb*NPTS + nn)) * 3;

    for (int kb = 0; kb < CIN; kb += 16) {
#pragma unroll
        for (int u = 0; u < 8; u++) {
            int c = kb + ac8 + u;
            float v;
            if (c < CFEAT)      v = frow[c];
            else if (c < CIN)   v = xrow[c - CFEAT];
            else                v = 0.0f;
            As[(ac8 + u)*128 + ar] = v;
        }
        {
            int k = kb + (tid >> 4);
            int col = colBase + (tid & 15)*8;
            if (k < CIN) {
                float4 w0 = *reinterpret_cast<const float4*>(&W[k*COUT + col]);
                float4 w1 = *reinterpret_cast<const float4*>(&W[k*COUT + col + 4]);
                *reinterpret_cast<float4*>(&Bs[(tid>>4)*128 + (tid&15)*8])     = w0;
                *reinterpret_cast<float4*>(&Bs[(tid>>4)*128 + (tid&15)*8 + 4]) = w1;
            } else {
                float4 z = make_float4(0,0,0,0);
                *reinterpret_cast<float4*>(&Bs[(tid>>4)*128 + (tid&15)*8])     = z;
                *reinterpret_cast<float4*>(&Bs[(tid>>4)*128 + (tid&15)*8 + 4]) = z;
            }
        }
        __syncthreads();
#pragma unroll
        for (int kk = 0; kk < 16; kk++) {
            float4 a0 = *reinterpret_cast<const float4*>(&As[kk*128 + ty*8]);
            float4 a1 = *reinterpret_cast<const float4*>(&As[kk*128 + ty*8 + 4]);
            float4 b0 = *reinterpret_cast<const float4*>(&Bs[kk*128 + tx*8]);
            float4 b1 = *reinterpret_cast<const float4*>(&Bs[kk*128 + tx*8 + 4]);
            float av[8] = {a0.x,a0.y,a0.z,a0.w,a1.x,a1.y,a1.z,a1.w};
            float bv[8] = {b0.x,b0.y,b0.z,b0.w,b1.x,b1.y,b1.z,b1.w};
#pragma unroll
            for (int i = 0; i < 8; i++)
#pragma unroll
                for (int jj = 0; jj < 8; jj++)
                    acc[i][jj] = fmaf(av[i], bv[jj], acc[i][jj]);
        }
        __syncthreads();
    }

#pragma unroll
    for (int i = 0; i < 8; i++) {
        int orow = rowBase + ty*8 + i;
        float* op = out + (size_t)orow * COUT + colBase + tx*8;
        *reinterpret_cast<float4*>(op)     = make_float4(acc[i][0], acc[i][1], acc[i][2], acc[i][3]);
        *reinterpret_cast<float4*>(op + 4) = make_float4(acc[i][4], acc[i][5], acc[i][6], acc[i][7]);
    }
}

// ---------------- Fused gather + max-pool + BN stats ----------------
__global__ __launch_bounds__(256)
void fuse_kernel(float* __restrict__ out_feat)
{
    const int tid = threadIdx.x;
    const int q0  = blockIdx.x * 8;
    float s1 = 0.0f, s2 = 0.0f;
    for (int jq = 0; jq < 8; jq++) {
        int q = q0 + jq;
        int b = q >> 11;
        float ct = g_CT[(size_t)q*COUT + tid];
        const int* kn = g_knn + q*KNN_K;
        float mv = -3.4e38f;
#pragma unroll
        for (int k = 0; k < KNN_K; k++) {
            int n = __ldg(kn + k);
            float g = g_G[((size_t)(b*NPTS + n))*COUT + tid];
            float h = g + ct;
            s1 += h;
            s2 = fmaf(h, h, s2);
            mv = fmaxf(mv, h);
        }
        out_feat[(size_t)q*COUT + tid] = mv;
    }
    atomicAdd(&g_sum[tid],   s1);
    atomicAdd(&g_sumsq[tid], s2);
}

// ---------------- BN apply ----------------
__global__ __launch_bounds__(256)
void bn_kernel(float* __restrict__ feat, const float* __restrict__ gamma,
               const float* __restrict__ beta)
{
    int i = blockIdx.x * blockDim.x + threadIdx.x;
    int o = i & (COUT - 1);
    const float inv = 1.0f / (float)TOTAL_CNT;
    float mean = g_sum[o] * inv;
    float var  = g_sumsq[o] * inv - mean*mean;
    float sc   = rsqrtf(var + BN_EPS) * gamma[o];
    float v    = (feat[i] - mean) * sc + beta[o];
    feat[i] = fmaxf(v, 0.0f);
}

// ---------------- launch ----------------
extern "C" void kernel_launch(void* const* d_in, const int* in_sizes, int n_in,
                              void* d_out, int out_size)
{
    const float* xyz    = (const float*)d_in[0];
    const float* feat   = (const float*)d_in[1];
    const float* conv_w = (const float*)d_in[2];
    const float* gamma  = (const float*)d_in[3];
    const float* beta   = (const float*)d_in[4];
    const int*   initf  = (const int*)d_in[5];
    (void)in_sizes; (void)n_in; (void)out_size;

    float* out      = (float*)d_out;
    float* out_xyz  = out;
    float* out_feat = out + NB*NPOINT*3;
    float* out_sidx = out + NB*NPOINT*3 + NB*NPOINT*COUT;

    cudaFuncSetAttribute(fps_kernel, cudaFuncAttributeMaxDynamicSharedMemorySize,
                         3*NPTS*sizeof(float));

    zero_stats_kernel<<<1, 256>>>();
    wd_kernel<<<(CIN*COUT + 255)/256, 256>>>(conv_w);
    fps_kernel<<<NB, 512, 3*NPTS*sizeof(float)>>>(xyz, initf, out_xyz, out_sidx);
    gemm_kernel<0><<<dim3(2, (NB*NPTS)/128), 256>>>(feat, xyz, conv_w);
    knn_kernel<<<NB*NPOINT, 256>>>(xyz);
    gemm_kernel<1><<<dim3(2, (NB*NPOINT)/128), 256>>>(feat, xyz, conv_w);
    fuse_kernel<<<(NB*NPOINT)/8, 256>>>(out_feat);
    bn_kernel<<<(NB*NPOINT*COUT)/256, 256>>>(out_feat, gamma, beta);
}